// round 16
// baseline (speedup 1.0000x reference)
#include <cuda_runtime.h>
#include <cub/block/block_radix_sort.cuh>
#include <cstdint>

constexpr int B   = 32;
constexpr int NV  = 32768;
constexpr int NF  = 65536;
constexpr int NVC = NV * 3;
constexpr int NVT = B * NV;
constexpr int NFT = B * NF;
constexpr int NBKT = B * NV;
constexpr long long IDS_ROW = 9LL * NF + 2;

constexpr long long OFF_IDS   = 0;
constexpr long long OFF_ATT   = OFF_IDS + (long long)B * IDS_ROW;
constexpr long long OFF_CODES = OFF_ATT + (long long)B * IDS_ROW;
constexpr long long OFF_DQ    = OFF_CODES + (long long)B * NF * 9;
constexpr long long OFF_SF    = OFF_DQ + (long long)B * NF * 9;

// PDL: dependent grids are dispatched while the primary runs; this wait
// releases when the primary completes. No-op cost if edge isn't programmatic.
#define GRID_DEP_WAIT() asm volatile("griddepcontrol.wait;" ::: "memory")

// ---------------- device scratch (symbol memory; kernel access only)
__device__ float               g_center[NVC];
__device__ unsigned            g_longest_bits = 0u;  // atomicMax of deterministic
                                                     // values: replay-idempotent
__device__ int                 g_is64;
__device__ unsigned            g_qp[NVT];
__device__ unsigned long long  g_vkA[NVT];
__device__ unsigned long long  g_vkB[NVT];
__device__ unsigned            g_vcnt[NVT];
__device__ unsigned            g_voff[NVT];
__device__ unsigned            g_vcoarse[256];  // 8 chunks x 32 batches
__device__ unsigned short      g_inv[NVT];
__device__ unsigned            g_qsp[NVT];
__device__ unsigned long long  g_fkA[NFT];
__device__ unsigned            g_fk32[NFT];
__device__ unsigned            g_cnt[NBKT];
__device__ unsigned            g_off[NBKT];
__device__ unsigned            g_fcoarse[256];
__device__ unsigned            g_med[65536];
__device__ unsigned            g_big[128];
__device__ unsigned            g_nmed;
__device__ unsigned            g_nbig;

__device__ __forceinline__ unsigned f2u(float f) {
    unsigned u = __float_as_uint(f);
    return (u & 0x80000000u) ? ~u : (u | 0x80000000u);
}
__device__ __forceinline__ float u2f(unsigned u) {
    unsigned bits = (u & 0x80000000u) ? (u & 0x7FFFFFFFu) : ~u;
    return __uint_as_float(bits);
}
__device__ __forceinline__ int zbucket(float vv) {
    int zq = (int)((vv + 0.5f) * 32768.0f);
    return zq < 0 ? 0 : (zq > 32767 ? 32767 : zq);
}

// ---------------- kernels ----------------

// min/max + center + longest; zero BOTH stage counters + coarse; dtype detect
__global__ void k_minmax(const float* __restrict__ v, const void* __restrict__ faces) {
    for (int z = blockIdx.x * 256 + threadIdx.x; z < NVT; z += gridDim.x * 256) {
        g_vcnt[z] = 0;
        g_cnt[z]  = 0;                          // face counters (NBKT==NVT)
    }
    int gt = blockIdx.x * 256 + threadIdx.x;
    if (gt < 256) { g_vcoarse[gt] = 0; g_fcoarse[gt] = 0; }
    if (gt == 0)  { g_nmed = 0u; g_nbig = 0u; }
    float mn = INFINITY, mx = -INFINITY;
    if (gt < NVC) {
#pragma unroll
        for (int b = 0; b < B; b++) {
            float x = v[(size_t)b * NVC + gt];
            mn = fminf(mn, x); mx = fmaxf(mx, x);
        }
        g_center[gt] = (mn + mx) * 0.5f;
    }
    float d = (gt < NVC) ? (mx - mn) : 0.0f;
    __shared__ float s[256];
    s[threadIdx.x] = d;
    __syncthreads();
    for (int o = 128; o > 0; o >>= 1) {
        if (threadIdx.x < o) s[threadIdx.x] = fmaxf(s[threadIdx.x], s[threadIdx.x + o]);
        __syncthreads();
    }
    if (threadIdx.x == 0) atomicMax(&g_longest_bits, __float_as_uint(s[0]));
    // faces dtype detect (512B read: in-bounds under either interpretation)
    if (blockIdx.x == 0 && threadIdx.x < 32) {
        const long long* f = (const long long*)faces;
        int ok = 1;
        for (int k = threadIdx.x; k < 64; k += 32) {
            int hi = (int)(f[k] >> 32);
            if (hi != 0 && hi != -1) ok = 0;
        }
        ok = __all_sync(0xFFFFFFFFu, ok);
        if (threadIdx.x == 0) g_is64 = ok;
    }
}

// attention_mask — side stream, overlaps the vertex pipeline
__global__ void k_att(const void* __restrict__ facesv, float* __restrict__ out) {
    __shared__ unsigned char mk_s[256];
    constexpr int BPB = NF / 256;
    int b  = blockIdx.x / BPB;
    int f0 = (blockIdx.x % BPB) * 256;
    int t  = threadIdx.x;
    size_t fb = ((size_t)b * NF + f0 + t) * 3;
    long long i0, i1, i2;
    if (g_is64) {
        const long long* fp = (const long long*)facesv;
        i0 = fp[fb + 0]; i1 = fp[fb + 1]; i2 = fp[fb + 2];
    } else {
        const int* fp = (const int*)facesv;
        i0 = fp[fb + 0]; i1 = fp[fb + 1]; i2 = fp[fb + 2];
    }
    mk_s[t] = ((i0 != -1) && (i1 != -1) && (i2 != -1)) ? 1 : 0;
    __syncthreads();
    long long amb = OFF_ATT + (long long)b * IDS_ROW + 1 + (long long)f0 * 9;
    for (int k = t; k < 256 * 9; k += 256)
        out[amb + k] = mk_s[k / 9] ? 1.0f : 0.0f;
    if (t == 0 && f0 == 0)
        out[OFF_ATT + (long long)b * IDS_ROW] = -1.0f;
    if (t == 0 && f0 == NF - 256)
        out[OFF_ATT + (long long)b * IDS_ROW + IDS_ROW - 1] = -1.0f;
}

// normalize (exact IEEE div), quantize (packed), u64 key + fine hist + smem-
// aggregated coarse hist (R13/R14: direct global adds to 256 addrs serialize)
__global__ void k_prep(const float* __restrict__ verts) {
    GRID_DEP_WAIT();
    __shared__ unsigned sCoarse[8];
    if (threadIdx.x < 8) sCoarse[threadIdx.x] = 0u;
    __syncthreads();
    int i = blockIdx.x * 256 + threadIdx.x;
    int b = i >> 15;
    int j = i & (NV - 1);
    float L = __uint_as_float(g_longest_bits);
    const float* p = verts + (size_t)b * NVC + (size_t)j * 3;
    unsigned ku[3], qp = 0;
    float vvz = 0.0f;
#pragma unroll
    for (int c = 0; c < 3; c++) {
        float x  = p[c];
        float vv = __fdiv_rn(x - g_center[j * 3 + c], L);
        ku[c] = f2u(vv);
        if (c == 2) vvz = vv;
        float tq = (vv + 1.0f) * 0.5f * 128.0f - 0.5f;   // pow2 muls: exact
        int q = (int)rintf(tq);                           // half-to-even == jnp.round
        q = q < 0 ? 0 : (q > 127 ? 127 : q);
        qp |= (unsigned)q << (c * 8);
    }
    g_qp[i] = qp;
    unsigned zp = ku[2] - 0x40000000u;                    // < 2^31 since |vv|<=0.5
    g_vkA[i] = ((unsigned long long)zp << 33) |
               ((unsigned long long)(ku[1] >> 14) << 15) |
               (unsigned long long)(i & 32767);
    int zq = zbucket(vvz);
    atomicAdd(&g_vcnt[(b << 15) | zq], 1u);
    atomicAdd(&sCoarse[zq >> 12], 1u);
    __syncthreads();
    if (threadIdx.x < 8 && sCoarse[threadIdx.x] != 0u)
        atomicAdd(&g_vcoarse[(b << 3) | threadIdx.x], sCoarse[threadIdx.x]);
}

// parallel per-batch scan: 8 blocks/batch (4096 counters, 4/thread), chunk
// base seeded from the coarse histogram. (Validated: 5.7-5.9 us, correct.)
__global__ void k_scan(const unsigned* __restrict__ cnt,
                       unsigned* __restrict__ off,
                       const unsigned* __restrict__ coarse, unsigned segTotal) {
    GRID_DEP_WAIT();
    __shared__ unsigned warpTot[32];
    __shared__ unsigned chunkBase;
    unsigned blk = blockIdx.x, b = blk >> 3, c = blk & 7;
    unsigned base = (b << 15) + (c << 12);
    unsigned t = threadIdx.x, lane = t & 31, wid = t >> 5;
    if (t == 0) {
        unsigned s = b * segTotal;
        for (unsigned k = 0; k < c; k++) s += coarse[(b << 3) + k];
        chunkBase = s;
    }
    uint4 x = ((const uint4*)(cnt + base))[t];
    unsigned tot = x.x + x.y + x.z + x.w;
    unsigned e1 = x.x, e2 = x.x + x.y, e3 = x.x + x.y + x.z;
    unsigned v = tot;
#pragma unroll
    for (int d = 1; d < 32; d <<= 1) {
        unsigned o = __shfl_up_sync(0xFFFFFFFFu, v, d);
        if (lane >= (unsigned)d) v += o;
    }
    if (lane == 31) warpTot[wid] = v;
    __syncthreads();
    if (wid == 0) {
        unsigned w = warpTot[lane];
        unsigned s = w;
#pragma unroll
        for (int d = 1; d < 32; d <<= 1) {
            unsigned o = __shfl_up_sync(0xFFFFFFFFu, s, d);
            if (lane >= (unsigned)d) s += o;
        }
        warpTot[lane] = s - w;
    }
    __syncthreads();
    unsigned tb = chunkBase + warpTot[wid] + (v - tot);
    uint4 o4;
    o4.x = tb; o4.y = tb + e1; o4.z = tb + e2; o4.w = tb + e3;
    ((uint4*)(off + base))[t] = o4;
}

// scatter vertex keys into buckets
__global__ void k_vscatter() {
    GRID_DEP_WAIT();
    int i = blockIdx.x * 256 + threadIdx.x;
    if (i >= NVT) return;
    unsigned long long key = g_vkA[i];
    float vvz = u2f((unsigned)(key >> 33) + 0x40000000u);  // exact (f2u bijective)
    unsigned bucket = ((unsigned)i >> 15 << 15) | (unsigned)zbucket(vvz);
    unsigned pos = atomicAdd(&g_voff[bucket], 1u);
    g_vkB[pos] = key;
}

__device__ __forceinline__ void v_emit(unsigned pos, unsigned long long key) {
    unsigned rank = pos & 32767u;
    unsigned g = (pos & ~32767u) | (unsigned)(key & 32767u);
    g_inv[g]   = (unsigned short)rank;
    g_qsp[pos] = g_qp[g];
}

// one thread per vertex bucket; n<=8 in registers (P(n>8)~1e-6 at lambda=1);
// >8 in-place global fallback (correctness-only)
__global__ void k_vsort() {
    GRID_DEP_WAIT();
    unsigned bkt = blockIdx.x * 256 + threadIdx.x;
    if (bkt >= (unsigned)NVT) return;
    unsigned n = g_vcnt[bkt];
    if (n == 0) return;
    unsigned base = g_voff[bkt] - n;      // g_voff advanced by exactly n
    if (n == 1) {
        v_emit(base, g_vkB[base]);
    } else if (n <= 8) {
        unsigned long long a[8];
        for (unsigned i = 0; i < n; i++) a[i] = g_vkB[base + i];
        for (unsigned i = 1; i < n; i++) {
            unsigned long long x = a[i];
            int j = (int)i - 1;
            while (j >= 0 && a[j] > x) { a[j + 1] = a[j]; j--; }
            a[j + 1] = x;
        }
        for (unsigned i = 0; i < n; i++) v_emit(base + i, a[i]);
    } else {                         // statistically absent; in-place global
        for (unsigned i = 1; i < n; i++) {
            unsigned long long x = g_vkB[base + i];
            int j = (int)i - 1;
            while (j >= 0 && g_vkB[base + j] > x) {
                g_vkB[base + j + 1] = g_vkB[base + j]; j--;
            }
            g_vkB[base + j + 1] = x;
        }
        for (unsigned i = 0; i < n; i++) v_emit(base + i, g_vkB[base + i]);
    }
}

// face keys + fine hist + smem-aggregated coarse hist (side branch)
__global__ void k_fkeys(const void* __restrict__ facesv) {
    __shared__ unsigned sCoarse[8];
    if (threadIdx.x < 8) sCoarse[threadIdx.x] = 0u;
    __syncthreads();
    int i = blockIdx.x * 256 + threadIdx.x;
    int b = i >> 16;               // NF = 65536
    size_t fb = (size_t)i * 3;
    long long i0, i1, i2;
    if (g_is64) {
        const long long* fp = (const long long*)facesv;
        i0 = fp[fb + 0]; i1 = fp[fb + 1]; i2 = fp[fb + 2];
    } else {
        const int* fp = (const int*)facesv;
        i0 = fp[fb + 0]; i1 = fp[fb + 1]; i2 = fp[fb + 2];
    }
    int base = b * NV;
    unsigned r0 = g_inv[base + ((int)i0 & (NV - 1))];
    unsigned r1 = g_inv[base + ((int)i1 & (NV - 1))];
    unsigned r2 = g_inv[base + ((int)i2 & (NV - 1))];
    unsigned long long key =
        ((unsigned long long)b << 45) |
        ((unsigned long long)r2 << 30) |
        ((unsigned long long)r1 << 15) |
        (unsigned long long)r0;
    g_fkA[i] = key;
    atomicAdd(&g_cnt[(unsigned)(key >> 30)], 1u);
    atomicAdd(&sCoarse[r2 >> 12], 1u);
    __syncthreads();
    if (threadIdx.x < 8 && sCoarse[threadIdx.x] != 0u)
        atomicAdd(&g_fcoarse[(b << 3) | threadIdx.x], sCoarse[threadIdx.x]);
}

// dq/codes/ids writes (225 MB) — stream 0, overlapped by the face-sort chain
__global__ void k_fout(const void* __restrict__ facesv, float* __restrict__ out) {
    __shared__ unsigned dq_s[256 * 3];
    __shared__ unsigned char mk_s[256];
    constexpr int BPB = NF / 256;
    int b  = blockIdx.x / BPB;
    int f0 = (blockIdx.x % BPB) * 256;
    int t  = threadIdx.x;
    int base = b * NV;

    size_t fb = ((size_t)b * NF + f0 + t) * 3;
    long long i0, i1, i2;
    if (g_is64) {
        const long long* fp = (const long long*)facesv;
        i0 = fp[fb + 0]; i1 = fp[fb + 1]; i2 = fp[fb + 2];
    } else {
        const int* fp = (const int*)facesv;
        i0 = fp[fb + 0]; i1 = fp[fb + 1]; i2 = fp[fb + 2];
    }
    bool mask = (i0 != -1) && (i1 != -1) && (i2 != -1);
    int s0 = mask ? ((int)i0 & (NV - 1)) : 0;
    int s1 = mask ? ((int)i1 & (NV - 1)) : 0;
    int s2 = mask ? ((int)i2 & (NV - 1)) : 0;
    dq_s[t * 3 + 0] = g_qsp[base + s0];
    dq_s[t * 3 + 1] = g_qsp[base + s1];
    dq_s[t * 3 + 2] = g_qsp[base + s2];
    mk_s[t] = mask ? 1 : 0;
    __syncthreads();

    long long dqb = OFF_DQ    + ((long long)b * NF + f0) * 9;
    long long cdb = OFF_CODES + ((long long)b * NF + f0) * 9;
    long long idb = OFF_IDS   + (long long)b * IDS_ROW + 1 + (long long)f0 * 9;

    float4* dq4 = (float4*)(out + dqb);
    float4* cd4 = (float4*)(out + cdb);
    for (int q = t; q < 576; q += 256) {
        int k = q * 4;
        float dv[4], cv[4];
#pragma unroll
        for (int e = 0; e < 4; e++) {
            int kk = k + e;
            int fl = kk / 9, c = kk % 9;
            float d = (float)((dq_s[fl * 3 + c / 3] >> ((c % 3) * 8)) & 0xFFu);
            dv[e] = d;
            cv[e] = mk_s[fl] ? d : -1.0f;
        }
        dq4[q] = make_float4(dv[0], dv[1], dv[2], dv[3]);
        cd4[q] = make_float4(cv[0], cv[1], cv[2], cv[3]);
    }
    for (int k = t; k < 256 * 9; k += 256) {
        int fl = k / 9, c = k % 9;
        float d = (float)((dq_s[fl * 3 + c / 3] >> ((c % 3) * 8)) & 0xFFu);
        out[idb + k] = mk_s[fl] ? d : -1.0f;
    }
    if (t == 0 && f0 == 0)
        out[OFF_IDS + (long long)b * IDS_ROW] = -1.0f;
    if (t == 0 && f0 == NF - 256)
        out[OFF_IDS + (long long)b * IDS_ROW + IDS_ROW - 1] = -1.0f;
}

// scatter faces: u32 payload (r1<<15|r0) — bucket implicit in position
__global__ void k_scatter() {
    GRID_DEP_WAIT();
    int i = blockIdx.x * 256 + threadIdx.x;
    if (i >= NFT) return;
    unsigned long long key = g_fkA[i];
    unsigned pos = atomicAdd(&g_off[(unsigned)(key >> 30)], 1u);
    g_fk32[pos] = (unsigned)(key & 0x3FFFFFFFull);
}

__device__ __forceinline__ void write_row(float* out, unsigned rank,
                                          unsigned payload, unsigned bkt) {
    long long o = OFF_SF + (long long)rank * 3;
    out[o + 0] = (float)(payload & 0x7FFFu);
    out[o + 1] = (float)((payload >> 15) & 0x7FFFu);
    out[o + 2] = (float)(bkt & 32767u);
}

__device__ __forceinline__ unsigned warp_bitonic32(unsigned v) {
    unsigned lane = threadIdx.x & 31;
#pragma unroll
    for (int k = 2; k <= 32; k <<= 1)
#pragma unroll
        for (int j = k >> 1; j > 0; j >>= 1) {
            unsigned o = __shfl_xor_sync(0xFFFFFFFFu, v, j);
            bool keepMin = (((lane & j) == 0) == ((lane & k) == 0));
            v = keepMin ? (v < o ? v : o) : (v > o ? v : o);
        }
    return v;
}

// one thread per face bucket: n<=12 inline (Poisson(2): med list ~empty)
__global__ void k_wsort(float* __restrict__ out) {
    GRID_DEP_WAIT();
    unsigned bkt = blockIdx.x * 256 + threadIdx.x;
    if (bkt >= (unsigned)NBKT) return;
    unsigned n = g_cnt[bkt];
    if (n == 0) return;
    unsigned base = g_off[bkt] - n;
    if (n <= 12) {
        unsigned a[12];
        for (unsigned i = 0; i < n; i++) a[i] = g_fk32[base + i];
        for (unsigned i = 1; i < n; i++) {
            unsigned x = a[i];
            int j = (int)i - 1;
            while (j >= 0 && a[j] > x) { a[j + 1] = a[j]; j--; }
            a[j + 1] = x;
        }
        for (unsigned i = 0; i < n; i++) write_row(out, base + i, a[i], bkt);
    } else if (n <= 32) {
        unsigned idx = atomicAdd(&g_nmed, 1u);
        if (idx < 65536u) g_med[idx] = bkt;
    } else {
        unsigned idx = atomicAdd(&g_nbig, 1u);
        if (idx < 128u) g_big[idx] = bkt;
    }
}

// face tail: blocks [0,96) warp-bitonic med; [96,128) BlockRadixSort big (pad)
__global__ void k_ftail(float* __restrict__ out) {
    GRID_DEP_WAIT();
    if (blockIdx.x < 96) {
        unsigned nwarp = 96u * 8u;
        unsigned lane  = threadIdx.x & 31;
        for (unsigned w = (blockIdx.x * 256 + threadIdx.x) >> 5;
             w < g_nmed; w += nwarp) {
            unsigned bkt  = g_med[w];
            unsigned n    = g_cnt[bkt];
            unsigned base = g_off[bkt] - n;
            unsigned v = (lane < n) ? g_fk32[base + lane] : 0xFFFFFFFFu;
            v = warp_bitonic32(v);
            if (lane < n) write_row(out, base + lane, v, bkt);
        }
    } else {
        typedef cub::BlockRadixSort<unsigned, 256, 32> Sorter;
        __shared__ typename Sorter::TempStorage ts;
        unsigned nbig = g_nbig;
        for (unsigned bi = blockIdx.x - 96; bi < nbig; bi += 32) {
            unsigned bkt  = g_big[bi];
            unsigned n    = g_cnt[bkt];
            unsigned base = g_off[bkt] - n;
            float r2f = (float)(bkt & 32767u);
            unsigned keys[32];
#pragma unroll
            for (int i = 0; i < 32; i++) {
                unsigned idx = threadIdx.x * 32 + i;
                keys[i] = (idx < n) ? g_fk32[base + idx] : 0xFFFFFFFFu;
            }
            Sorter(ts).Sort(keys);
#pragma unroll
            for (int i = 0; i < 32; i++) {
                unsigned rank = threadIdx.x * 32 + i;
                if (rank < n) {
                    long long o = OFF_SF + (long long)(base + rank) * 3;
                    out[o + 0] = (float)(keys[i] & 0x7FFFu);
                    out[o + 1] = (float)((keys[i] >> 15) & 0x7FFFu);
                    out[o + 2] = r2f;
                }
            }
            __syncthreads();
        }
    }
}

// ---------------- host ----------------

template <typename... Args>
static void launch_pdl(void (*kern)(Args...), int grid, int block,
                       cudaStream_t s, Args... args) {
    cudaLaunchConfig_t cfg = {};
    cfg.gridDim = dim3(grid);
    cfg.blockDim = dim3(block);
    cfg.stream = s;
    cudaLaunchAttribute at[1];
    at[0].id = cudaLaunchAttributeProgrammaticStreamSerialization;
    at[0].val.programmaticStreamSerializationAllowed = 1;
    cfg.attrs = at;
    cfg.numAttrs = 1;
    cudaLaunchKernelEx(&cfg, kern, args...);
}

extern "C" void kernel_launch(void* const* d_in, const int* in_sizes, int n_in,
                              void* d_out, int out_size) {
    const float* verts = (const float*)d_in[0];
    const void*  faces = (const void*)d_in[1];
    float*       out   = (float*)d_out;

    void *p_vcnt, *p_voff, *p_vco, *p_cnt, *p_off, *p_fco;
    cudaGetSymbolAddress(&p_vcnt, g_vcnt);
    cudaGetSymbolAddress(&p_voff, g_voff);
    cudaGetSymbolAddress(&p_vco,  g_vcoarse);
    cudaGetSymbolAddress(&p_cnt,  g_cnt);
    cudaGetSymbolAddress(&p_off,  g_off);
    cudaGetSymbolAddress(&p_fco,  g_fcoarse);

    // side stream + events (created per call, NOT destroyed: destroying a
    // joined stream mid-capture invalidates the capture)
    cudaStream_t s1;
    cudaStreamCreateWithFlags(&s1, cudaStreamNonBlocking);
    cudaEvent_t eFork, eV, eB;
    cudaEventCreateWithFlags(&eFork, cudaEventDisableTiming);
    cudaEventCreateWithFlags(&eV,    cudaEventDisableTiming);
    cudaEventCreateWithFlags(&eB,    cudaEventDisableTiming);

    // critical path: minmax ->PDL prep ->PDL scan ->PDL vscatter ->PDL vsort -> fout
    k_minmax<<<(NVC + 255) / 256, 256>>>(verts, faces);
    launch_pdl(k_prep, NVT / 256, 256, (cudaStream_t)0, verts);

    // branch 1: attention_mask (eFork after prep keeps minmax->prep a PDL
    // edge; k_att has ~50us of slack before branch 2 needs s1)
    cudaEventRecord(eFork, 0);
    cudaStreamWaitEvent(s1, eFork, 0);
    k_att<<<B * (NF / 256), 256, 0, s1>>>(faces, out);

    launch_pdl(k_scan, 256, 1024, (cudaStream_t)0,
               (const unsigned*)p_vcnt, (unsigned*)p_voff,
               (const unsigned*)p_vco, (unsigned)NV);
    launch_pdl(k_vscatter, NVT / 256, 256, (cudaStream_t)0);
    launch_pdl(k_vsort, NVT / 256, 256, (cudaStream_t)0);

    // branch 2: face-sort chain (PDL within the chain) overlaps k_fout
    cudaEventRecord(eV, 0);
    cudaStreamWaitEvent(s1, eV, 0);
    k_fkeys<<<NFT / 256, 256, 0, s1>>>(faces);
    launch_pdl(k_scan, 256, 1024, s1,
               (const unsigned*)p_cnt, (unsigned*)p_off,
               (const unsigned*)p_fco, (unsigned)NF);
    launch_pdl(k_scatter, NFT / 256, 256, s1);
    launch_pdl(k_wsort, NBKT / 256, 256, s1, out);
    launch_pdl(k_ftail, 128, 256, s1, out);
    cudaEventRecord(eB, s1);

    k_fout<<<B * (NF / 256), 256>>>(faces, out);

    cudaStreamWaitEvent(0, eB, 0);   // join

    (void)in_sizes; (void)n_in; (void)out_size;
}

// round 17
// speedup vs baseline: 1.0646x; 1.0646x over previous
#include <cuda_runtime.h>
#include <cub/block/block_radix_sort.cuh>
#include <cstdint>

constexpr int B   = 32;
constexpr int NV  = 32768;
constexpr int NF  = 65536;
constexpr int NVC = NV * 3;
constexpr int NVT = B * NV;
constexpr int NFT = B * NF;
constexpr int NBKT = B * NV;
constexpr long long IDS_ROW = 9LL * NF + 2;

constexpr long long OFF_IDS   = 0;
constexpr long long OFF_ATT   = OFF_IDS + (long long)B * IDS_ROW;
constexpr long long OFF_CODES = OFF_ATT + (long long)B * IDS_ROW;
constexpr long long OFF_DQ    = OFF_CODES + (long long)B * NF * 9;
constexpr long long OFF_SF    = OFF_DQ + (long long)B * NF * 9;

// ---------------- device scratch (symbol memory; kernel access only)
__device__ float               g_center[NVC];
__device__ unsigned            g_longest_bits = 0u;  // atomicMax of deterministic
                                                     // values: replay-idempotent
__device__ int                 g_is64;
__device__ unsigned            g_qp[NVT];
__device__ unsigned long long  g_vkA[NVT];
__device__ unsigned long long  g_vkB[NVT];
__device__ unsigned            g_vcnt[NVT];
__device__ unsigned            g_voff[NVT];
__device__ unsigned            g_vcoarse[256];  // 8 chunks x 32 batches
__device__ unsigned short      g_inv[NVT];
__device__ unsigned            g_qsp[NVT];
__device__ unsigned long long  g_fkA[NFT];
__device__ unsigned            g_fk32[NFT];
__device__ unsigned            g_cnt[NBKT];
__device__ unsigned            g_off[NBKT];
__device__ unsigned            g_fcoarse[256];
__device__ unsigned            g_med[65536];
__device__ unsigned            g_big[128];
__device__ unsigned            g_nmed;
__device__ unsigned            g_nbig;

__device__ __forceinline__ unsigned f2u(float f) {
    unsigned u = __float_as_uint(f);
    return (u & 0x80000000u) ? ~u : (u | 0x80000000u);
}
__device__ __forceinline__ float u2f(unsigned u) {
    unsigned bits = (u & 0x80000000u) ? (u & 0x7FFFFFFFu) : ~u;
    return __uint_as_float(bits);
}
__device__ __forceinline__ int zbucket(float vv) {
    int zq = (int)((vv + 0.5f) * 32768.0f);
    return zq < 0 ? 0 : (zq > 32767 ? 32767 : zq);
}

// ---------------- kernels ----------------

// min/max + center + longest; zero vertex counters + coarse; dtype detect
__global__ void k_minmax(const float* __restrict__ v, const void* __restrict__ faces) {
    for (int z = blockIdx.x * 256 + threadIdx.x; z < NVT; z += gridDim.x * 256)
        g_vcnt[z] = 0;
    int gt = blockIdx.x * 256 + threadIdx.x;
    if (gt < 256) { g_vcoarse[gt] = 0; g_fcoarse[gt] = 0; }
    float mn = INFINITY, mx = -INFINITY;
    if (gt < NVC) {
#pragma unroll
        for (int b = 0; b < B; b++) {
            float x = v[(size_t)b * NVC + gt];
            mn = fminf(mn, x); mx = fmaxf(mx, x);
        }
        g_center[gt] = (mn + mx) * 0.5f;
    }
    float d = (gt < NVC) ? (mx - mn) : 0.0f;
    __shared__ float s[256];
    s[threadIdx.x] = d;
    __syncthreads();
    for (int o = 128; o > 0; o >>= 1) {
        if (threadIdx.x < o) s[threadIdx.x] = fmaxf(s[threadIdx.x], s[threadIdx.x + o]);
        __syncthreads();
    }
    if (threadIdx.x == 0) atomicMax(&g_longest_bits, __float_as_uint(s[0]));
    // faces dtype detect (512B read: in-bounds under either interpretation)
    if (blockIdx.x == 0 && threadIdx.x < 32) {
        const long long* f = (const long long*)faces;
        int ok = 1;
        for (int k = threadIdx.x; k < 64; k += 32) {
            int hi = (int)(f[k] >> 32);
            if (hi != 0 && hi != -1) ok = 0;
        }
        ok = __all_sync(0xFFFFFFFFu, ok);
        if (threadIdx.x == 0) g_is64 = ok;
    }
}

// attention_mask — side stream, overlaps the vertex pipeline (streaming stores)
__global__ void k_att(const void* __restrict__ facesv, float* __restrict__ out) {
    __shared__ unsigned char mk_s[256];
    constexpr int BPB = NF / 256;
    int b  = blockIdx.x / BPB;
    int f0 = (blockIdx.x % BPB) * 256;
    int t  = threadIdx.x;
    size_t fb = ((size_t)b * NF + f0 + t) * 3;
    long long i0, i1, i2;
    if (g_is64) {
        const long long* fp = (const long long*)facesv;
        i0 = fp[fb + 0]; i1 = fp[fb + 1]; i2 = fp[fb + 2];
    } else {
        const int* fp = (const int*)facesv;
        i0 = fp[fb + 0]; i1 = fp[fb + 1]; i2 = fp[fb + 2];
    }
    mk_s[t] = ((i0 != -1) && (i1 != -1) && (i2 != -1)) ? 1 : 0;
    __syncthreads();
    long long amb = OFF_ATT + (long long)b * IDS_ROW + 1 + (long long)f0 * 9;
    for (int k = t; k < 256 * 9; k += 256)
        __stcs(&out[amb + k], mk_s[k / 9] ? 1.0f : 0.0f);
    if (t == 0 && f0 == 0)
        __stcs(&out[OFF_ATT + (long long)b * IDS_ROW], -1.0f);
    if (t == 0 && f0 == NF - 256)
        __stcs(&out[OFF_ATT + (long long)b * IDS_ROW + IDS_ROW - 1], -1.0f);
}

// normalize (exact IEEE div), quantize (packed), u64 key + fine hist + smem-
// aggregated coarse hist (R13/R14: direct global adds to 256 addrs serialize)
__global__ void k_prep(const float* __restrict__ verts) {
    __shared__ unsigned sCoarse[8];
    if (threadIdx.x < 8) sCoarse[threadIdx.x] = 0u;
    __syncthreads();
    int i = blockIdx.x * 256 + threadIdx.x;
    int b = i >> 15;
    int j = i & (NV - 1);
    float L = __uint_as_float(g_longest_bits);
    const float* p = verts + (size_t)b * NVC + (size_t)j * 3;
    unsigned ku[3], qp = 0;
    float vvz = 0.0f;
#pragma unroll
    for (int c = 0; c < 3; c++) {
        float x  = p[c];
        float vv = __fdiv_rn(x - g_center[j * 3 + c], L);
        ku[c] = f2u(vv);
        if (c == 2) vvz = vv;
        float tq = (vv + 1.0f) * 0.5f * 128.0f - 0.5f;   // pow2 muls: exact
        int q = (int)rintf(tq);                           // half-to-even == jnp.round
        q = q < 0 ? 0 : (q > 127 ? 127 : q);
        qp |= (unsigned)q << (c * 8);
    }
    g_qp[i] = qp;
    unsigned zp = ku[2] - 0x40000000u;                    // < 2^31 since |vv|<=0.5
    g_vkA[i] = ((unsigned long long)zp << 33) |
               ((unsigned long long)(ku[1] >> 14) << 15) |
               (unsigned long long)(i & 32767);
    int zq = zbucket(vvz);
    atomicAdd(&g_vcnt[(b << 15) | zq], 1u);
    atomicAdd(&sCoarse[zq >> 12], 1u);
    __syncthreads();
    if (threadIdx.x < 8 && sCoarse[threadIdx.x] != 0u)
        atomicAdd(&g_vcoarse[(b << 3) | threadIdx.x], sCoarse[threadIdx.x]);
}

// parallel per-batch scan: 8 blocks/batch (4096 counters, 4/thread), chunk
// base seeded from the coarse histogram. (Validated: 5.7-5.9 us, correct.)
__global__ void k_scan(const unsigned* __restrict__ cnt,
                       unsigned* __restrict__ off,
                       const unsigned* __restrict__ coarse, unsigned segTotal) {
    __shared__ unsigned warpTot[32];
    __shared__ unsigned chunkBase;
    unsigned blk = blockIdx.x, b = blk >> 3, c = blk & 7;
    unsigned base = (b << 15) + (c << 12);
    unsigned t = threadIdx.x, lane = t & 31, wid = t >> 5;
    if (t == 0) {
        unsigned s = b * segTotal;
        for (unsigned k = 0; k < c; k++) s += coarse[(b << 3) + k];
        chunkBase = s;
    }
    uint4 x = ((const uint4*)(cnt + base))[t];
    unsigned tot = x.x + x.y + x.z + x.w;
    unsigned e1 = x.x, e2 = x.x + x.y, e3 = x.x + x.y + x.z;
    unsigned v = tot;
#pragma unroll
    for (int d = 1; d < 32; d <<= 1) {
        unsigned o = __shfl_up_sync(0xFFFFFFFFu, v, d);
        if (lane >= (unsigned)d) v += o;
    }
    if (lane == 31) warpTot[wid] = v;
    __syncthreads();
    if (wid == 0) {
        unsigned w = warpTot[lane];
        unsigned s = w;
#pragma unroll
        for (int d = 1; d < 32; d <<= 1) {
            unsigned o = __shfl_up_sync(0xFFFFFFFFu, s, d);
            if (lane >= (unsigned)d) s += o;
        }
        warpTot[lane] = s - w;
    }
    __syncthreads();
    unsigned tb = chunkBase + warpTot[wid] + (v - tot);
    uint4 o4;
    o4.x = tb; o4.y = tb + e1; o4.z = tb + e2; o4.w = tb + e3;
    ((uint4*)(off + base))[t] = o4;
}

// scatter vertex keys into buckets; zero face-stage counters
__global__ void k_vscatter() {
    int i = blockIdx.x * 256 + threadIdx.x;
    if (i >= NVT) return;
    g_cnt[i] = 0;
    if (i == 0) { g_nmed = 0u; g_nbig = 0u; }
    unsigned long long key = g_vkA[i];
    float vvz = u2f((unsigned)(key >> 33) + 0x40000000u);  // exact (f2u bijective)
    unsigned bucket = ((unsigned)i >> 15 << 15) | (unsigned)zbucket(vvz);
    unsigned pos = atomicAdd(&g_voff[bucket], 1u);
    g_vkB[pos] = key;
}

__device__ __forceinline__ void v_emit(unsigned pos, unsigned long long key) {
    unsigned rank = pos & 32767u;
    unsigned g = (pos & ~32767u) | (unsigned)(key & 32767u);
    g_inv[g]   = (unsigned short)rank;
    g_qsp[pos] = g_qp[g];
}

// one thread per vertex bucket, ALL sizes inline (lambda = 1: P(n>8) ~ 1e-6;
// >32 path is a correctness-only fallback)
__global__ void k_vsort() {
    unsigned bkt = blockIdx.x * 256 + threadIdx.x;
    if (bkt >= (unsigned)NVT) return;
    unsigned n = g_vcnt[bkt];
    if (n == 0) return;
    unsigned base = g_voff[bkt] - n;      // g_voff advanced by exactly n
    if (n == 1) {
        v_emit(base, g_vkB[base]);
    } else if (n <= 32) {
        unsigned long long a[32];
        for (unsigned i = 0; i < n; i++) a[i] = g_vkB[base + i];
        for (unsigned i = 1; i < n; i++) {
            unsigned long long x = a[i];
            int j = (int)i - 1;
            while (j >= 0 && a[j] > x) { a[j + 1] = a[j]; j--; }
            a[j + 1] = x;
        }
        for (unsigned i = 0; i < n; i++) v_emit(base + i, a[i]);
    } else {                         // statistically absent; in-place global
        for (unsigned i = 1; i < n; i++) {
            unsigned long long x = g_vkB[base + i];
            int j = (int)i - 1;
            while (j >= 0 && g_vkB[base + j] > x) {
                g_vkB[base + j + 1] = g_vkB[base + j]; j--;
            }
            g_vkB[base + j + 1] = x;
        }
        for (unsigned i = 0; i < n; i++) v_emit(base + i, g_vkB[base + i]);
    }
}

// face keys + fine hist + smem-aggregated coarse hist (side branch)
__global__ void k_fkeys(const void* __restrict__ facesv) {
    __shared__ unsigned sCoarse[8];
    if (threadIdx.x < 8) sCoarse[threadIdx.x] = 0u;
    __syncthreads();
    int i = blockIdx.x * 256 + threadIdx.x;
    int b = i >> 16;               // NF = 65536
    size_t fb = (size_t)i * 3;
    long long i0, i1, i2;
    if (g_is64) {
        const long long* fp = (const long long*)facesv;
        i0 = fp[fb + 0]; i1 = fp[fb + 1]; i2 = fp[fb + 2];
    } else {
        const int* fp = (const int*)facesv;
        i0 = fp[fb + 0]; i1 = fp[fb + 1]; i2 = fp[fb + 2];
    }
    int base = b * NV;
    unsigned r0 = g_inv[base + ((int)i0 & (NV - 1))];
    unsigned r1 = g_inv[base + ((int)i1 & (NV - 1))];
    unsigned r2 = g_inv[base + ((int)i2 & (NV - 1))];
    unsigned long long key =
        ((unsigned long long)b << 45) |
        ((unsigned long long)r2 << 30) |
        ((unsigned long long)r1 << 15) |
        (unsigned long long)r0;
    g_fkA[i] = key;
    atomicAdd(&g_cnt[(unsigned)(key >> 30)], 1u);
    atomicAdd(&sCoarse[r2 >> 12], 1u);
    __syncthreads();
    if (threadIdx.x < 8 && sCoarse[threadIdx.x] != 0u)
        atomicAdd(&g_fcoarse[(b << 3) | threadIdx.x], sCoarse[threadIdx.x]);
}

// dq/codes/ids writes (225 MB) — stream 0, streaming stores keep L2 free for
// the concurrent face-sort chain's random-access working set
__global__ void k_fout(const void* __restrict__ facesv, float* __restrict__ out) {
    __shared__ unsigned dq_s[256 * 3];
    __shared__ unsigned char mk_s[256];
    constexpr int BPB = NF / 256;
    int b  = blockIdx.x / BPB;
    int f0 = (blockIdx.x % BPB) * 256;
    int t  = threadIdx.x;
    int base = b * NV;

    size_t fb = ((size_t)b * NF + f0 + t) * 3;
    long long i0, i1, i2;
    if (g_is64) {
        const long long* fp = (const long long*)facesv;
        i0 = fp[fb + 0]; i1 = fp[fb + 1]; i2 = fp[fb + 2];
    } else {
        const int* fp = (const int*)facesv;
        i0 = fp[fb + 0]; i1 = fp[fb + 1]; i2 = fp[fb + 2];
    }
    bool mask = (i0 != -1) && (i1 != -1) && (i2 != -1);
    int s0 = mask ? ((int)i0 & (NV - 1)) : 0;
    int s1 = mask ? ((int)i1 & (NV - 1)) : 0;
    int s2 = mask ? ((int)i2 & (NV - 1)) : 0;
    dq_s[t * 3 + 0] = g_qsp[base + s0];
    dq_s[t * 3 + 1] = g_qsp[base + s1];
    dq_s[t * 3 + 2] = g_qsp[base + s2];
    mk_s[t] = mask ? 1 : 0;
    __syncthreads();

    long long dqb = OFF_DQ    + ((long long)b * NF + f0) * 9;
    long long cdb = OFF_CODES + ((long long)b * NF + f0) * 9;
    long long idb = OFF_IDS   + (long long)b * IDS_ROW + 1 + (long long)f0 * 9;

    float4* dq4 = (float4*)(out + dqb);
    float4* cd4 = (float4*)(out + cdb);
    for (int q = t; q < 576; q += 256) {
        int k = q * 4;
        float dv[4], cv[4];
#pragma unroll
        for (int e = 0; e < 4; e++) {
            int kk = k + e;
            int fl = kk / 9, c = kk % 9;
            float d = (float)((dq_s[fl * 3 + c / 3] >> ((c % 3) * 8)) & 0xFFu);
            dv[e] = d;
            cv[e] = mk_s[fl] ? d : -1.0f;
        }
        __stcs(&dq4[q], make_float4(dv[0], dv[1], dv[2], dv[3]));
        __stcs(&cd4[q], make_float4(cv[0], cv[1], cv[2], cv[3]));
    }
    for (int k = t; k < 256 * 9; k += 256) {
        int fl = k / 9, c = k % 9;
        float d = (float)((dq_s[fl * 3 + c / 3] >> ((c % 3) * 8)) & 0xFFu);
        __stcs(&out[idb + k], mk_s[fl] ? d : -1.0f);
    }
    if (t == 0 && f0 == 0)
        __stcs(&out[OFF_IDS + (long long)b * IDS_ROW], -1.0f);
    if (t == 0 && f0 == NF - 256)
        __stcs(&out[OFF_IDS + (long long)b * IDS_ROW + IDS_ROW - 1], -1.0f);
}

// scatter faces: u32 payload (r1<<15|r0) — bucket implicit in position
__global__ void k_scatter() {
    int i = blockIdx.x * 256 + threadIdx.x;
    if (i >= NFT) return;
    unsigned long long key = g_fkA[i];
    unsigned pos = atomicAdd(&g_off[(unsigned)(key >> 30)], 1u);
    g_fk32[pos] = (unsigned)(key & 0x3FFFFFFFull);
}

__device__ __forceinline__ void write_row(float* out, unsigned rank,
                                          unsigned payload, unsigned bkt) {
    long long o = OFF_SF + (long long)rank * 3;
    __stcs(&out[o + 0], (float)(payload & 0x7FFFu));
    __stcs(&out[o + 1], (float)((payload >> 15) & 0x7FFFu));
    __stcs(&out[o + 2], (float)(bkt & 32767u));
}

__device__ __forceinline__ unsigned warp_bitonic32(unsigned v) {
    unsigned lane = threadIdx.x & 31;
#pragma unroll
    for (int k = 2; k <= 32; k <<= 1)
#pragma unroll
        for (int j = k >> 1; j > 0; j >>= 1) {
            unsigned o = __shfl_xor_sync(0xFFFFFFFFu, v, j);
            bool keepMin = (((lane & j) == 0) == ((lane & k) == 0));
            v = keepMin ? (v < o ? v : o) : (v > o ? v : o);
        }
    return v;
}

// one thread per face bucket: n<=12 inline (Poisson(2): med list ~empty)
__global__ void k_wsort(float* __restrict__ out) {
    unsigned bkt = blockIdx.x * 256 + threadIdx.x;
    if (bkt >= (unsigned)NBKT) return;
    unsigned n = g_cnt[bkt];
    if (n == 0) return;
    unsigned base = g_off[bkt] - n;
    if (n <= 12) {
        unsigned a[12];
        for (unsigned i = 0; i < n; i++) a[i] = g_fk32[base + i];
        for (unsigned i = 1; i < n; i++) {
            unsigned x = a[i];
            int j = (int)i - 1;
            while (j >= 0 && a[j] > x) { a[j + 1] = a[j]; j--; }
            a[j + 1] = x;
        }
        for (unsigned i = 0; i < n; i++) write_row(out, base + i, a[i], bkt);
    } else if (n <= 32) {
        unsigned idx = atomicAdd(&g_nmed, 1u);
        if (idx < 65536u) g_med[idx] = bkt;
    } else {
        unsigned idx = atomicAdd(&g_nbig, 1u);
        if (idx < 128u) g_big[idx] = bkt;
    }
}

// face tail: blocks [0,96) warp-bitonic med; [96,128) BlockRadixSort big (pad)
__global__ void k_ftail(float* __restrict__ out) {
    if (blockIdx.x < 96) {
        unsigned nwarp = 96u * 8u;
        unsigned lane  = threadIdx.x & 31;
        for (unsigned w = (blockIdx.x * 256 + threadIdx.x) >> 5;
             w < g_nmed; w += nwarp) {
            unsigned bkt  = g_med[w];
            unsigned n    = g_cnt[bkt];
            unsigned base = g_off[bkt] - n;
            unsigned v = (lane < n) ? g_fk32[base + lane] : 0xFFFFFFFFu;
            v = warp_bitonic32(v);
            if (lane < n) write_row(out, base + lane, v, bkt);
        }
    } else {
        typedef cub::BlockRadixSort<unsigned, 256, 32> Sorter;
        __shared__ typename Sorter::TempStorage ts;
        unsigned nbig = g_nbig;
        for (unsigned bi = blockIdx.x - 96; bi < nbig; bi += 32) {
            unsigned bkt  = g_big[bi];
            unsigned n    = g_cnt[bkt];
            unsigned base = g_off[bkt] - n;
            float r2f = (float)(bkt & 32767u);
            unsigned keys[32];
#pragma unroll
            for (int i = 0; i < 32; i++) {
                unsigned idx = threadIdx.x * 32 + i;
                keys[i] = (idx < n) ? g_fk32[base + idx] : 0xFFFFFFFFu;
            }
            Sorter(ts).Sort(keys);
#pragma unroll
            for (int i = 0; i < 32; i++) {
                unsigned rank = threadIdx.x * 32 + i;
                if (rank < n) {
                    long long o = OFF_SF + (long long)(base + rank) * 3;
                    __stcs(&out[o + 0], (float)(keys[i] & 0x7FFFu));
                    __stcs(&out[o + 1], (float)((keys[i] >> 15) & 0x7FFFu));
                    __stcs(&out[o + 2], r2f);
                }
            }
            __syncthreads();
        }
    }
}

// ---------------- host ----------------

extern "C" void kernel_launch(void* const* d_in, const int* in_sizes, int n_in,
                              void* d_out, int out_size) {
    const float* verts = (const float*)d_in[0];
    const void*  faces = (const void*)d_in[1];
    float*       out   = (float*)d_out;

    void *p_vcnt, *p_voff, *p_vco, *p_cnt, *p_off, *p_fco;
    cudaGetSymbolAddress(&p_vcnt, g_vcnt);
    cudaGetSymbolAddress(&p_voff, g_voff);
    cudaGetSymbolAddress(&p_vco,  g_vcoarse);
    cudaGetSymbolAddress(&p_cnt,  g_cnt);
    cudaGetSymbolAddress(&p_off,  g_off);
    cudaGetSymbolAddress(&p_fco,  g_fcoarse);

    // side stream + events (created per call, NOT destroyed: destroying a
    // joined stream mid-capture invalidates the capture)
    cudaStream_t s1;
    cudaStreamCreateWithFlags(&s1, cudaStreamNonBlocking);
    cudaEvent_t eFork, eV, eB;
    cudaEventCreateWithFlags(&eFork, cudaEventDisableTiming);
    cudaEventCreateWithFlags(&eV,    cudaEventDisableTiming);
    cudaEventCreateWithFlags(&eB,    cudaEventDisableTiming);

    // critical path: minmax -> prep -> scan -> vscatter -> vsort -> fout
    k_minmax<<<(NVC + 255) / 256, 256>>>(verts, faces);

    // branch 1: attention_mask overlaps the vertex pipeline
    cudaEventRecord(eFork, 0);
    cudaStreamWaitEvent(s1, eFork, 0);
    k_att<<<B * (NF / 256), 256, 0, s1>>>(faces, out);

    k_prep<<<NVT / 256, 256>>>(verts);
    k_scan<<<256, 1024>>>((const unsigned*)p_vcnt, (unsigned*)p_voff,
                          (const unsigned*)p_vco, (unsigned)NV);
    k_vscatter<<<NVT / 256, 256>>>();
    k_vsort<<<NVT / 256, 256>>>();

    // branch 2: full face-sort chain overlaps k_fout
    cudaEventRecord(eV, 0);
    cudaStreamWaitEvent(s1, eV, 0);
    k_fkeys<<<NFT / 256, 256, 0, s1>>>(faces);
    k_scan<<<256, 1024, 0, s1>>>((const unsigned*)p_cnt, (unsigned*)p_off,
                                 (const unsigned*)p_fco, (unsigned)NF);
    k_scatter<<<NFT / 256, 256, 0, s1>>>();
    k_wsort<<<NBKT / 256, 256, 0, s1>>>(out);
    k_ftail<<<128, 256, 0, s1>>>(out);
    cudaEventRecord(eB, s1);

    k_fout<<<B * (NF / 256), 256>>>(faces, out);

    cudaStreamWaitEvent(0, eB, 0);   // join

    (void)in_sizes; (void)n_in; (void)out_size;
}